// round 12
// baseline (speedup 1.0000x reference)
#include <cuda_runtime.h>
#include <cuda_bf16.h>
#include <cstdint>

#define N_NODES 100000
#define N_EDGES 1600000
#define D 128
#define N_LAYERS 4
#define ROWU32 128          // 256 bf16 per activation row = 128 uint32

// ---------------- scratch (__device__ globals; no allocation) ----------------
__device__ float g_bufA[N_NODES * D];
__device__ float g_bufB[N_NODES * D];
__device__ float g_invdeg[N_NODES];
__device__ int   g_deg[N_NODES];
__device__ int   g_cursor[N_NODES];
__device__ int   g_rowstart[N_NODES + 1];
__device__ int   g_csr_src[N_EDGES];
// Packed bf16 activations [row][k2]: k2<64 = agg-half, >=64 = x-half
__device__ uint32_t g_Ahi[(size_t)N_NODES * ROWU32];
__device__ uint32_t g_Alo[(size_t)N_NODES * ROWU32];
// Packed bf16 weights [l][j][k2] combined (k<128 -> Wl, k>=128 -> Wr)
__device__ uint32_t g_Whi[N_LAYERS * D * ROWU32];
__device__ uint32_t g_Wlo[N_LAYERS * D * ROWU32];

// ------------------------------ helpers -------------------------------------
__device__ __forceinline__ uint32_t smem_u32(const void* p) {
    uint32_t a;
    asm("{ .reg .u64 t; cvta.to.shared.u64 t, %1; cvt.u32.u64 %0, t; }"
        : "=r"(a) : "l"(p));
    return a;
}
__device__ __forceinline__ void cp16(uint32_t saddr, const void* g) {
    asm volatile("cp.async.ca.shared.global [%0], [%1], 16;"
                 :: "r"(saddr), "l"(g) : "memory");
}
#define CP_COMMIT() asm volatile("cp.async.commit_group;" ::: "memory")
#define CP_WAIT(n)  asm volatile("cp.async.wait_group %0;" :: "n"(n) : "memory")

__device__ __forceinline__ uint32_t pack_bf16(__nv_bfloat16 a, __nv_bfloat16 b) {
    return ((uint32_t)__bfloat16_as_ushort(b) << 16) | (uint32_t)__bfloat16_as_ushort(a);
}
__device__ __forceinline__ void split_bf16(float x, __nv_bfloat16& h, __nv_bfloat16& l) {
    h = __float2bfloat16(x);
    l = __float2bfloat16(x - __bfloat162float(h));
}

__device__ __forceinline__ void mma_bf16(float c[4], const uint32_t a[4],
                                         uint32_t b0, uint32_t b1) {
    asm volatile(
        "mma.sync.aligned.m16n8k16.row.col.f32.bf16.bf16.f32 "
        "{%0,%1,%2,%3}, {%4,%5,%6,%7}, {%8,%9}, {%0,%1,%2,%3};"
        : "+f"(c[0]), "+f"(c[1]), "+f"(c[2]), "+f"(c[3])
        : "r"(a[0]), "r"(a[1]), "r"(a[2]), "r"(a[3]), "r"(b0), "r"(b1));
}

// ---------------------------------------------------------------------------
// Setup kernels
// ---------------------------------------------------------------------------
__global__ void deg_kernel(const int* __restrict__ dst, int* __restrict__ deg) {
    int e = blockIdx.x * blockDim.x + threadIdx.x;
    if (e < N_EDGES) atomicAdd(&deg[dst[e]], 1);
}

// scan also zeroes cursor (fill runs after)
__global__ void scan_kernel(const int* __restrict__ deg,
                            int* __restrict__ row_start,
                            float* __restrict__ invdeg,
                            int* __restrict__ cursor) {
    __shared__ int sm[1024];
    const int t = threadIdx.x;
    const int CH = (N_NODES + 1023) / 1024;
    const int base = t * CH;
    int s = 0;
    for (int i = 0; i < CH; i++) {
        int idx = base + i;
        if (idx < N_NODES) s += deg[idx];
    }
    sm[t] = s;
    __syncthreads();
    for (int d = 1; d < 1024; d <<= 1) {
        int v = (t >= d) ? sm[t - d] : 0;
        __syncthreads();
        sm[t] += v;
        __syncthreads();
    }
    int off = sm[t] - s;
    for (int i = 0; i < CH; i++) {
        int idx = base + i;
        if (idx < N_NODES) {
            row_start[idx] = off;
            int dg = deg[idx];
            off += dg;
            invdeg[idx] = 1.0f / fmaxf((float)dg, 1.0f);
            cursor[idx] = 0;
        }
    }
    if (t == 1023) row_start[N_NODES] = off;
}

// fill: CSR fill + W hi/lo split (non-permuted, R8 format)
__global__ void fill_kernel(const int* __restrict__ src,
                            const int* __restrict__ dst,
                            const int* __restrict__ row_start,
                            int* __restrict__ cursor,
                            int* __restrict__ csr_src,
                            const float* __restrict__ Wl,
                            const float* __restrict__ Wr,
                            uint32_t* __restrict__ Whi,
                            uint32_t* __restrict__ Wlo) {
    int e = blockIdx.x * blockDim.x + threadIdx.x;
    if (e < N_EDGES) {
        int d = dst[e];
        int p = atomicAdd(&cursor[d], 1);
        csr_src[row_start[d] + p] = src[e];
    }
    if (e < N_LAYERS * D * ROWU32) {
        int k2 = e & (ROWU32 - 1);
        int j  = (e >> 7) & (D - 1);
        int l  = e >> 14;
        int k0 = 2 * k2, k1 = 2 * k2 + 1;
        float w0 = (k0 < D) ? Wl[(l * D + j) * D + k0] : Wr[(l * D + j) * D + (k0 - D)];
        float w1 = (k1 < D) ? Wl[(l * D + j) * D + k1] : Wr[(l * D + j) * D + (k1 - D)];
        __nv_bfloat16 h0, l0, h1, l1;
        split_bf16(w0, h0, l0);
        split_bf16(w1, h1, l1);
        Whi[e] = pack_bf16(h0, h1);
        Wlo[e] = pack_bf16(l0, l1);
    }
}

// ---------------------------------------------------------------------------
// FUSED layer kernel: phase 1 = gather-mean + bf16 split for this CTA's 128
// rows (written to global, L2-resident); phase 2 = R8 GEMM (CTA 128x128,
// 8 warps 32x64, K=256 in 8 cp.async double-buffered chunks) + bias + ReLU.
// With 2 CTAs/SM, one CTA's phase-1 memory work overlaps the other's MMAs.
// ---------------------------------------------------------------------------
#define SAP 20                        // uint32 row stride (16 used), R8-proven
#define ARR_SZ (128 * SAP)            // 2560 uint32 = 10240 B per operand array
#define BUF_SZ (4 * ARR_SZ)           // Ah|Al|Bh|Bl
#define GEMM_SMEM (2 * BUF_SZ * 4)    // 81920 B

__global__ __launch_bounds__(256, 2)
void layer_kernel(const float4* __restrict__ xin4,
                  const int* __restrict__ csr_src,
                  const int* __restrict__ row_start,
                  const float* __restrict__ invdeg,
                  uint32_t* __restrict__ Ahi,
                  uint32_t* __restrict__ Alo,
                  const uint32_t* __restrict__ Whi,
                  const uint32_t* __restrict__ Wlo,
                  const float* __restrict__ bl,
                  float* __restrict__ xout) {
    extern __shared__ uint32_t smem[];
    const uint32_t sbase = smem_u32(smem);
    const int t = threadIdx.x;
    const int lane = t & 31;
    const int w = t >> 5;
    const int row0 = blockIdx.x * 128;

    // ================= phase 1: gather + split own 128 rows =================
    // warp w owns rows row0 + w*16 .. +15 (R8 gather loop per node)
    for (int ni = 0; ni < 16; ni++) {
        int node = w * 16 + ni + row0;
        if (node >= N_NODES) break;
        int b = row_start[node];
        int e = row_start[node + 1];
        float4 acc = make_float4(0.f, 0.f, 0.f, 0.f);
        for (int j = b; j < e; j += 32) {
            int cnt = min(32, e - j);
            int sreg = (lane < cnt) ? csr_src[j + lane] : 0;
            for (int i = 0; i < cnt; i++) {
                int si = __shfl_sync(0xffffffffu, sreg, i);
                float4 v = __ldg(xin4 + (long long)si * 32 + lane);
                acc.x += v.x; acc.y += v.y; acc.z += v.z; acc.w += v.w;
            }
        }
        float sc = invdeg[node];
        acc.x *= sc; acc.y *= sc; acc.z *= sc; acc.w *= sc;
        long long rb = (long long)node * ROWU32;
        __nv_bfloat16 h0, l0, h1, l1, h2, l2, h3, l3;
        split_bf16(acc.x, h0, l0); split_bf16(acc.y, h1, l1);
        split_bf16(acc.z, h2, l2); split_bf16(acc.w, h3, l3);
        *(uint2*)(Ahi + rb + 2 * lane) = make_uint2(pack_bf16(h0, h1), pack_bf16(h2, h3));
        *(uint2*)(Alo + rb + 2 * lane) = make_uint2(pack_bf16(l0, l1), pack_bf16(l2, l3));
        // own x row -> x-half
        float4 mine = __ldg(xin4 + (long long)node * 32 + lane);
        split_bf16(mine.x, h0, l0); split_bf16(mine.y, h1, l1);
        split_bf16(mine.z, h2, l2); split_bf16(mine.w, h3, l3);
        *(uint2*)(Ahi + rb + 64 + 2 * lane) = make_uint2(pack_bf16(h0, h1), pack_bf16(h2, h3));
        *(uint2*)(Alo + rb + 64 + 2 * lane) = make_uint2(pack_bf16(l0, l1), pack_bf16(l2, l3));
    }
    __syncthreads();

    // ======================= phase 2: R8 GEMM ==============================
    const int wr = (w >> 1) * 32;     // warp row offset
    const int wc = (w & 1) * 64;      // warp col offset
    const int qr = lane >> 2;
    const int qc = lane & 3;

    float c[2][8][4];
#pragma unroll
    for (int ma = 0; ma < 2; ma++)
#pragma unroll
        for (int na = 0; na < 8; na++)
#pragma unroll
            for (int q = 0; q < 4; q++) c[ma][na][q] = 0.0f;

    auto load_chunk = [&](int i, int b) {
        uint32_t bb = sbase + (uint32_t)(b * BUF_SZ * 4);
#pragma unroll
        for (int s = 0; s < 8; s++) {
            int slot = t + s * 256;
            int arr = slot >> 9;
            int rem = slot & 511;
            int r = rem >> 2;
            int g = rem & 3;
            uint32_t saddr = bb + (uint32_t)(arr * ARR_SZ * 4 + r * (SAP * 4) + g * 16);
            const uint32_t* gp;
            if (arr < 2) {
                int rg = row0 + r;
                if (rg >= N_NODES) rg = N_NODES - 1;
                const uint32_t* basep = arr == 0 ? Ahi : Alo;
                gp = basep + (long long)rg * ROWU32 + i * 16 + g * 4;
            } else {
                const uint32_t* basep = arr == 2 ? Whi : Wlo;
                gp = basep + r * ROWU32 + i * 16 + g * 4;
            }
            cp16(saddr, gp);
        }
        CP_COMMIT();
    };

    load_chunk(0, 0);

    for (int i = 0; i < 8; i++) {
        const int b = i & 1;
        if (i < 7) load_chunk(i + 1, b ^ 1);
        if (i < 7) CP_WAIT(1); else CP_WAIT(0);
        __syncthreads();

        const uint32_t* Ah = smem + b * BUF_SZ;
        const uint32_t* Al = Ah + ARR_SZ;
        const uint32_t* Bh = Al + ARR_SZ;
        const uint32_t* Bl = Bh + ARR_SZ;

#pragma unroll
        for (int ks = 0; ks < 2; ks++) {
            const int k2b = ks * 8;
            uint32_t ah[2][4], al[2][4];
#pragma unroll
            for (int ma = 0; ma < 2; ma++) {
                int base = (wr + ma * 16 + qr) * SAP + k2b + qc;
                ah[ma][0] = Ah[base];           al[ma][0] = Al[base];
                ah[ma][1] = Ah[base + 8 * SAP]; al[ma][1] = Al[base + 8 * SAP];
                ah[ma][2] = Ah[base + 4];       al[ma][2] = Al[base + 4];
                ah[ma][3] = Ah[base + 8 * SAP + 4]; al[ma][3] = Al[base + 8 * SAP + 4];
            }
#pragma unroll
            for (int na = 0; na < 8; na++) {
                int boff = (wc + na * 8 + qr) * SAP + k2b + qc;
                uint32_t bh0 = Bh[boff], bh1 = Bh[boff + 4];
                uint32_t bl0 = Bl[boff], bl1 = Bl[boff + 4];
#pragma unroll
                for (int ma = 0; ma < 2; ma++) {
                    mma_bf16(c[ma][na], ah[ma], bh0, bh1);  // hi*hi
                    mma_bf16(c[ma][na], ah[ma], bl0, bl1);  // hi*lo
                    mma_bf16(c[ma][na], al[ma], bh0, bh1);  // lo*hi
                }
            }
        }
        __syncthreads();
    }

    // ---- epilogue: bias + relu + fp32 store ----
#pragma unroll
    for (int na = 0; na < 8; na++) {
        int col = wc + na * 8 + 2 * qc;
        float b0 = __ldg(bl + col), b1 = __ldg(bl + col + 1);
#pragma unroll
        for (int ma = 0; ma < 2; ma++) {
            int r0 = row0 + wr + ma * 16 + qr;
            int r1 = r0 + 8;
            if (r0 < N_NODES) {
                float2 o;
                o.x = fmaxf(c[ma][na][0] + b0, 0.f);
                o.y = fmaxf(c[ma][na][1] + b1, 0.f);
                *(float2*)(xout + (long long)r0 * D + col) = o;
            }
            if (r1 < N_NODES) {
                float2 o;
                o.x = fmaxf(c[ma][na][2] + b0, 0.f);
                o.y = fmaxf(c[ma][na][3] + b1, 0.f);
                *(float2*)(xout + (long long)r1 * D + col) = o;
            }
        }
    }
}

// ---------------------------------------------------------------------------
// kernel_launch
// ---------------------------------------------------------------------------
extern "C" void kernel_launch(void* const* d_in, const int* in_sizes, int n_in,
                              void* d_out, int out_size) {
    const float* x  = (const float*)d_in[0];
    const int*   ei = (const int*)  d_in[1];
    const float* Wl = (const float*)d_in[2];
    const float* bl = (const float*)d_in[3];
    const float* Wr = (const float*)d_in[4];
    float* out = (float*)d_out;

    const int* src = ei;
    const int* dst = ei + N_EDGES;

    float *bufA, *bufB, *invdeg;
    int *deg, *cursor, *rowstart, *csr_src;
    uint32_t *ahi, *alo, *whi, *wlo;
    cudaGetSymbolAddress((void**)&bufA,     g_bufA);
    cudaGetSymbolAddress((void**)&bufB,     g_bufB);
    cudaGetSymbolAddress((void**)&invdeg,   g_invdeg);
    cudaGetSymbolAddress((void**)&deg,      g_deg);
    cudaGetSymbolAddress((void**)&cursor,   g_cursor);
    cudaGetSymbolAddress((void**)&rowstart, g_rowstart);
    cudaGetSymbolAddress((void**)&csr_src,  g_csr_src);
    cudaGetSymbolAddress((void**)&ahi,      g_Ahi);
    cudaGetSymbolAddress((void**)&alo,      g_Alo);
    cudaGetSymbolAddress((void**)&whi,      g_Whi);
    cudaGetSymbolAddress((void**)&wlo,      g_Wlo);

    cudaFuncSetAttribute(layer_kernel,
                         cudaFuncAttributeMaxDynamicSharedMemorySize, GEMM_SMEM);

    cudaMemsetAsync(deg, 0, N_NODES * sizeof(int));
    deg_kernel<<<(N_EDGES + 255) / 256, 256>>>(dst, deg);
    scan_kernel<<<1, 1024>>>(deg, rowstart, invdeg, cursor);
    fill_kernel<<<(N_EDGES + 255) / 256, 256>>>(src, dst, rowstart,
                                                cursor, csr_src,
                                                Wl, Wr, whi, wlo);

    const int blocks = (N_NODES + 127) / 128;

    const float* cur = x;
    float* outs[N_LAYERS] = {bufA, bufB, bufA, out};

    for (int l = 0; l < N_LAYERS; l++) {
        layer_kernel<<<blocks, 256, GEMM_SMEM>>>(
            (const float4*)cur, csr_src, rowstart, invdeg,
            ahi, alo,
            whi + (size_t)l * D * ROWU32,
            wlo + (size_t)l * D * ROWU32,
            bl + (size_t)l * D,
            outs[l]);
        cur = outs[l];
    }
}

// round 13
// speedup vs baseline: 1.4876x; 1.4876x over previous
#include <cuda_runtime.h>
#include <cuda_bf16.h>
#include <cstdint>

#define N_NODES 100000
#define N_EDGES 1600000
#define D 128
#define N_LAYERS 4
#define ROWU32 128          // 256 bf16 per activation row = 128 uint32

// ---------------- scratch (__device__ globals; no allocation) ----------------
__device__ float g_bufA[N_NODES * D];
__device__ float g_bufB[N_NODES * D];
__device__ float g_invdeg[N_NODES];
__device__ int   g_deg[N_NODES];
__device__ int   g_cursor[N_NODES];
__device__ int   g_rowstart[N_NODES + 1];
__device__ int   g_csr_src[N_EDGES];
// Packed bf16 activations [row][k2]: k2<64 = agg-half, >=64 = x-half
__device__ uint32_t g_Ahi[(size_t)N_NODES * ROWU32];
__device__ uint32_t g_Alo[(size_t)N_NODES * ROWU32];
// Packed bf16 weights [l][j][k2] combined (k<128 -> Wl, k>=128 -> Wr)
__device__ uint32_t g_Whi[N_LAYERS * D * ROWU32];
__device__ uint32_t g_Wlo[N_LAYERS * D * ROWU32];

// ------------------------------ helpers -------------------------------------
__device__ __forceinline__ uint32_t smem_u32(const void* p) {
    uint32_t a;
    asm("{ .reg .u64 t; cvta.to.shared.u64 t, %1; cvt.u32.u64 %0, t; }"
        : "=r"(a) : "l"(p));
    return a;
}
__device__ __forceinline__ void cp16(uint32_t saddr, const void* g) {
    asm volatile("cp.async.ca.shared.global [%0], [%1], 16;"
                 :: "r"(saddr), "l"(g) : "memory");
}
#define CP_COMMIT() asm volatile("cp.async.commit_group;" ::: "memory")
#define CP_WAIT(n)  asm volatile("cp.async.wait_group %0;" :: "n"(n) : "memory")

__device__ __forceinline__ uint32_t pack_bf16(__nv_bfloat16 a, __nv_bfloat16 b) {
    return ((uint32_t)__bfloat16_as_ushort(b) << 16) | (uint32_t)__bfloat16_as_ushort(a);
}
__device__ __forceinline__ void split_bf16(float x, __nv_bfloat16& h, __nv_bfloat16& l) {
    h = __float2bfloat16(x);
    l = __float2bfloat16(x - __bfloat162float(h));
}

__device__ __forceinline__ void mma_bf16(float c[4], const uint32_t a[4],
                                         uint32_t b0, uint32_t b1) {
    asm volatile(
        "mma.sync.aligned.m16n8k16.row.col.f32.bf16.bf16.f32 "
        "{%0,%1,%2,%3}, {%4,%5,%6,%7}, {%8,%9}, {%0,%1,%2,%3};"
        : "+f"(c[0]), "+f"(c[1]), "+f"(c[2]), "+f"(c[3])
        : "r"(a[0]), "r"(a[1]), "r"(a[2]), "r"(a[3]), "r"(b0), "r"(b1));
}

// ---------------------------------------------------------------------------
// Setup kernels (R8 verbatim)
// ---------------------------------------------------------------------------
__global__ void deg_kernel(const int* __restrict__ dst, int* __restrict__ deg) {
    int e = blockIdx.x * blockDim.x + threadIdx.x;
    if (e < N_EDGES) atomicAdd(&deg[dst[e]], 1);
}

__global__ void scan_kernel(const int* __restrict__ deg,
                            int* __restrict__ row_start,
                            float* __restrict__ invdeg,
                            int* __restrict__ cursor) {
    __shared__ int sm[1024];
    const int t = threadIdx.x;
    const int CH = (N_NODES + 1023) / 1024;
    const int base = t * CH;
    int s = 0;
    for (int i = 0; i < CH; i++) {
        int idx = base + i;
        if (idx < N_NODES) s += deg[idx];
    }
    sm[t] = s;
    __syncthreads();
    for (int d = 1; d < 1024; d <<= 1) {
        int v = (t >= d) ? sm[t - d] : 0;
        __syncthreads();
        sm[t] += v;
        __syncthreads();
    }
    int off = sm[t] - s;
    for (int i = 0; i < CH; i++) {
        int idx = base + i;
        if (idx < N_NODES) {
            row_start[idx] = off;
            int dg = deg[idx];
            off += dg;
            invdeg[idx] = 1.0f / fmaxf((float)dg, 1.0f);
            cursor[idx] = 0;
        }
    }
    if (t == 1023) row_start[N_NODES] = off;
}

__global__ void fill_kernel(const int* __restrict__ src,
                            const int* __restrict__ dst,
                            const int* __restrict__ row_start,
                            int* __restrict__ cursor,
                            int* __restrict__ csr_src,
                            const float* __restrict__ Wl,
                            const float* __restrict__ Wr,
                            uint32_t* __restrict__ Whi,
                            uint32_t* __restrict__ Wlo) {
    int e = blockIdx.x * blockDim.x + threadIdx.x;
    if (e < N_EDGES) {
        int d = dst[e];
        int p = atomicAdd(&cursor[d], 1);
        csr_src[row_start[d] + p] = src[e];
    }
    if (e < N_LAYERS * D * ROWU32) {
        int k2 = e & (ROWU32 - 1);
        int j  = (e >> 7) & (D - 1);
        int l  = e >> 14;
        int k0 = 2 * k2, k1 = 2 * k2 + 1;
        float w0 = (k0 < D) ? Wl[(l * D + j) * D + k0] : Wr[(l * D + j) * D + (k0 - D)];
        float w1 = (k1 < D) ? Wl[(l * D + j) * D + k1] : Wr[(l * D + j) * D + (k1 - D)];
        __nv_bfloat16 h0, l0, h1, l1;
        split_bf16(w0, h0, l0);
        split_bf16(w1, h1, l1);
        Whi[e] = pack_bf16(h0, h1);
        Wlo[e] = pack_bf16(l0, l1);
    }
}

// ---------------------------------------------------------------------------
// Gather-mean -> packed bf16 hi/lo agg-half + own-x x-half (R8 verbatim)
// ---------------------------------------------------------------------------
__global__ __launch_bounds__(256)
void gather_kernel(const float4* __restrict__ x4,
                   const int* __restrict__ csr_src,
                   const int* __restrict__ row_start,
                   const float* __restrict__ invdeg,
                   uint32_t* __restrict__ Ahi,
                   uint32_t* __restrict__ Alo) {
    int warp = (blockIdx.x * blockDim.x + threadIdx.x) >> 5;
    int lane = threadIdx.x & 31;
    if (warp >= N_NODES) return;
    int b = row_start[warp];
    int e = row_start[warp + 1];
    float4 acc = make_float4(0.f, 0.f, 0.f, 0.f);
    for (int j = b; j < e; j += 32) {
        int cnt = min(32, e - j);
        int sreg = (lane < cnt) ? csr_src[j + lane] : 0;
        for (int i = 0; i < cnt; i++) {
            int si = __shfl_sync(0xffffffffu, sreg, i);
            float4 v = __ldg(x4 + (long long)si * 32 + lane);
            acc.x += v.x; acc.y += v.y; acc.z += v.z; acc.w += v.w;
        }
    }
    float sc = invdeg[warp];
    acc.x *= sc; acc.y *= sc; acc.z *= sc; acc.w *= sc;
    long long rb = (long long)warp * ROWU32;
    __nv_bfloat16 h0, l0, h1, l1, h2, l2, h3, l3;
    split_bf16(acc.x, h0, l0); split_bf16(acc.y, h1, l1);
    split_bf16(acc.z, h2, l2); split_bf16(acc.w, h3, l3);
    *(uint2*)(Ahi + rb + 2 * lane) = make_uint2(pack_bf16(h0, h1), pack_bf16(h2, h3));
    *(uint2*)(Alo + rb + 2 * lane) = make_uint2(pack_bf16(l0, l1), pack_bf16(l2, l3));
    // own x row -> x-half
    float4 mine = __ldg(x4 + (long long)warp * 32 + lane);
    split_bf16(mine.x, h0, l0); split_bf16(mine.y, h1, l1);
    split_bf16(mine.z, h2, l2); split_bf16(mine.w, h3, l3);
    *(uint2*)(Ahi + rb + 64 + 2 * lane) = make_uint2(pack_bf16(h0, h1), pack_bf16(h2, h3));
    *(uint2*)(Alo + rb + 64 + 2 * lane) = make_uint2(pack_bf16(l0, l1), pack_bf16(l2, l3));
}

// ---------------------------------------------------------------------------
// 3-term bf16 mma.sync GEMM + bias + ReLU.
// NEW SHAPE: CTA 64(M) x 128(N), 8 warps, warp tile 16x64. 32 accum regs.
// K=256 (128 k2) in 8 chunks of 16 k2, cp.async double-buffered.
// smem 60KB/CTA + ~75 regs -> 3 CTAs/SM = 24 warps (was 16): occupancy is
// the binding constraint per R12 profile (tensor pipe 87% idle at 16 warps).
// ---------------------------------------------------------------------------
#define SAP 20                          // uint32 row stride (16 used)
#define ARR_A (64 * SAP)                // 1280 u32 = 5120 B (Ah or Al)
#define ARR_B (128 * SAP)               // 2560 u32 = 10240 B (Bh or Bl)
#define BUF_SZ (2 * ARR_A + 2 * ARR_B)  // 7680 u32 = 30720 B
#define GEMM_SMEM (2 * BUF_SZ * 4)      // 61440 B

__global__ __launch_bounds__(256, 3)
void gemm_relu_kernel(const uint32_t* __restrict__ Ahi,
                      const uint32_t* __restrict__ Alo,
                      const uint32_t* __restrict__ Whi,
                      const uint32_t* __restrict__ Wlo,
                      const float* __restrict__ bl,
                      float* __restrict__ xout) {
    extern __shared__ uint32_t smem[];
    const uint32_t sbase = smem_u32(smem);
    const int t = threadIdx.x;
    const int lane = t & 31;
    const int w = t >> 5;
    const int wr = (w >> 1) * 16;     // warp row offset (4 groups x 16 rows)
    const int wc = (w & 1) * 64;      // warp col offset
    const int qr = lane >> 2;
    const int qc = lane & 3;
    const int row0 = blockIdx.x * 64;

    float c[8][4];
#pragma unroll
    for (int na = 0; na < 8; na++)
#pragma unroll
        for (int q = 0; q < 4; q++) c[na][q] = 0.0f;

    // 1536 16B-slots per chunk (A: 2x64x4, B: 2x128x4) -> 6 cp.async/thread
    auto load_chunk = [&](int i, int b) {
        uint32_t bb = sbase + (uint32_t)(b * BUF_SZ * 4);
#pragma unroll
        for (int s = 0; s < 6; s++) {
            int slot = t + s * 256;        // 0..1535
            uint32_t saddr;
            const uint32_t* gp;
            if (slot < 512) {              // A: arr 0=Ahi,1=Alo
                int arr = slot >> 8;
                int rem = slot & 255;
                int r = rem >> 2;
                int g = rem & 3;
                saddr = bb + (uint32_t)(arr * ARR_A * 4 + r * (SAP * 4) + g * 16);
                int rg = row0 + r;
                if (rg >= N_NODES) rg = N_NODES - 1;
                const uint32_t* basep = arr == 0 ? Ahi : Alo;
                gp = basep + (long long)rg * ROWU32 + i * 16 + g * 4;
            } else {                       // B: arr 0=Whi,1=Wlo
                int sb2 = slot - 512;
                int arr = sb2 >> 9;
                int rem = sb2 & 511;
                int r = rem >> 2;
                int g = rem & 3;
                saddr = bb + (uint32_t)((2 * ARR_A + arr * ARR_B) * 4 + r * (SAP * 4) + g * 16);
                const uint32_t* basep = arr == 0 ? Whi : Wlo;
                gp = basep + r * ROWU32 + i * 16 + g * 4;
            }
            cp16(saddr, gp);
        }
        CP_COMMIT();
    };

    load_chunk(0, 0);

    for (int i = 0; i < 8; i++) {
        const int b = i & 1;
        if (i < 7) load_chunk(i + 1, b ^ 1);
        if (i < 7) CP_WAIT(1); else CP_WAIT(0);
        __syncthreads();

        const uint32_t* Ah = smem + b * BUF_SZ;
        const uint32_t* Al = Ah + ARR_A;
        const uint32_t* Bh = Al + ARR_A;
        const uint32_t* Bl = Bh + ARR_B;

#pragma unroll
        for (int ks = 0; ks < 2; ks++) {
            const int k2b = ks * 8;
            int abase = (wr + qr) * SAP + k2b + qc;
            uint32_t ah[4], al[4];
            ah[0] = Ah[abase];               al[0] = Al[abase];
            ah[1] = Ah[abase + 8 * SAP];     al[1] = Al[abase + 8 * SAP];
            ah[2] = Ah[abase + 4];           al[2] = Al[abase + 4];
            ah[3] = Ah[abase + 8 * SAP + 4]; al[3] = Al[abase + 8 * SAP + 4];
#pragma unroll
            for (int na = 0; na < 8; na++) {
                int boff = (wc + na * 8 + qr) * SAP + k2b + qc;
                uint32_t bh0 = Bh[boff], bh1 = Bh[boff + 4];
                uint32_t bl0 = Bl[boff], bl1 = Bl[boff + 4];
                mma_bf16(c[na], ah, bh0, bh1);  // hi*hi
                mma_bf16(c[na], ah, bl0, bl1);  // hi*lo
                mma_bf16(c[na], al, bh0, bh1);  // lo*hi
            }
        }
        __syncthreads();
    }

    // ---- epilogue: bias + relu + fp32 store ----
#pragma unroll
    for (int na = 0; na < 8; na++) {
        int col = wc + na * 8 + 2 * qc;
        float b0 = __ldg(bl + col), b1 = __ldg(bl + col + 1);
        int r0 = row0 + wr + qr;
        int r1 = r0 + 8;
        if (r0 < N_NODES) {
            float2 o;
            o.x = fmaxf(c[na][0] + b0, 0.f);
            o.y = fmaxf(c[na][1] + b1, 0.f);
            *(float2*)(xout + (long long)r0 * D + col) = o;
        }
        if (r1 < N_NODES) {
            float2 o;
            o.x = fmaxf(c[na][2] + b0, 0.f);
            o.y = fmaxf(c[na][3] + b1, 0.f);
            *(float2*)(xout + (long long)r1 * D + col) = o;
        }
    }
}

// ---------------------------------------------------------------------------
// kernel_launch
// ---------------------------------------------------------------------------
extern "C" void kernel_launch(void* const* d_in, const int* in_sizes, int n_in,
                              void* d_out, int out_size) {
    const float* x  = (const float*)d_in[0];
    const int*   ei = (const int*)  d_in[1];
    const float* Wl = (const float*)d_in[2];
    const float* bl = (const float*)d_in[3];
    const float* Wr = (const float*)d_in[4];
    float* out = (float*)d_out;

    const int* src = ei;
    const int* dst = ei + N_EDGES;

    float *bufA, *bufB, *invdeg;
    int *deg, *cursor, *rowstart, *csr_src;
    uint32_t *ahi, *alo, *whi, *wlo;
    cudaGetSymbolAddress((void**)&bufA,     g_bufA);
    cudaGetSymbolAddress((void**)&bufB,     g_bufB);
    cudaGetSymbolAddress((void**)&invdeg,   g_invdeg);
    cudaGetSymbolAddress((void**)&deg,      g_deg);
    cudaGetSymbolAddress((void**)&cursor,   g_cursor);
    cudaGetSymbolAddress((void**)&rowstart, g_rowstart);
    cudaGetSymbolAddress((void**)&csr_src,  g_csr_src);
    cudaGetSymbolAddress((void**)&ahi,      g_Ahi);
    cudaGetSymbolAddress((void**)&alo,      g_Alo);
    cudaGetSymbolAddress((void**)&whi,      g_Whi);
    cudaGetSymbolAddress((void**)&wlo,      g_Wlo);

    cudaFuncSetAttribute(gemm_relu_kernel,
                         cudaFuncAttributeMaxDynamicSharedMemorySize, GEMM_SMEM);

    cudaMemsetAsync(deg, 0, N_NODES * sizeof(int));
    deg_kernel<<<(N_EDGES + 255) / 256, 256>>>(dst, deg);
    scan_kernel<<<1, 1024>>>(deg, rowstart, invdeg, cursor);
    fill_kernel<<<(N_EDGES + 255) / 256, 256>>>(src, dst, rowstart,
                                                cursor, csr_src,
                                                Wl, Wr, whi, wlo);

    const int gather_blocks = (N_NODES * 32 + 255) / 256;
    const int gemm_blocks = (N_NODES + 63) / 64;

    const float* cur = x;
    float* outs[N_LAYERS] = {bufA, bufB, bufA, out};

    for (int l = 0; l < N_LAYERS; l++) {
        gather_kernel<<<gather_blocks, 256>>>((const float4*)cur, csr_src,
                                              rowstart, invdeg, ahi, alo);
        gemm_relu_kernel<<<gemm_blocks, 256, GEMM_SMEM>>>(
            ahi, alo,
            whi + (size_t)l * D * ROWU32,
            wlo + (size_t)l * D * ROWU32,
            bl + (size_t)l * D,
            outs[l]);
        cur = outs[l];
    }
}

// round 14
// speedup vs baseline: 1.5778x; 1.0606x over previous
#include <cuda_runtime.h>
#include <cuda_bf16.h>
#include <cstdint>

#define N_NODES 100000
#define N_EDGES 1600000
#define D 128
#define N_LAYERS 4
#define ROWU32 128          // 256 bf16 per activation row = 128 uint32

// ---------------- scratch (__device__ globals; no allocation) ----------------
__device__ float g_bufA[N_NODES * D];
__device__ float g_bufB[N_NODES * D];
__device__ float g_invdeg[N_NODES];
__device__ int   g_deg[N_NODES];
__device__ int   g_cursor[N_NODES];
__device__ int   g_rowstart[N_NODES + 1];
__device__ int   g_csr_src[N_EDGES];
// Packed bf16 activations [row][k2]: k2<64 = agg-half, >=64 = x-half
__device__ uint32_t g_Ahi[(size_t)N_NODES * ROWU32];
__device__ uint32_t g_Alo[(size_t)N_NODES * ROWU32];
// Packed bf16 weights [l][j][k2] combined (k<128 -> Wl, k>=128 -> Wr)
__device__ uint32_t g_Whi[N_LAYERS * D * ROWU32];
__device__ uint32_t g_Wlo[N_LAYERS * D * ROWU32];

// ------------------------------ helpers -------------------------------------
__device__ __forceinline__ uint32_t smem_u32(const void* p) {
    uint32_t a;
    asm("{ .reg .u64 t; cvta.to.shared.u64 t, %1; cvt.u32.u64 %0, t; }"
        : "=r"(a) : "l"(p));
    return a;
}
__device__ __forceinline__ void cp16(uint32_t saddr, const void* g) {
    asm volatile("cp.async.ca.shared.global [%0], [%1], 16;"
                 :: "r"(saddr), "l"(g) : "memory");
}
#define CP_COMMIT() asm volatile("cp.async.commit_group;" ::: "memory")
#define CP_WAIT(n)  asm volatile("cp.async.wait_group %0;" :: "n"(n) : "memory")

__device__ __forceinline__ uint32_t pack_bf16(__nv_bfloat16 a, __nv_bfloat16 b) {
    return ((uint32_t)__bfloat16_as_ushort(b) << 16) | (uint32_t)__bfloat16_as_ushort(a);
}
__device__ __forceinline__ void split_bf16(float x, __nv_bfloat16& h, __nv_bfloat16& l) {
    h = __float2bfloat16(x);
    l = __float2bfloat16(x - __bfloat162float(h));
}

__device__ __forceinline__ void mma_bf16(float c[4], const uint32_t a[4],
                                         uint32_t b0, uint32_t b1) {
    asm volatile(
        "mma.sync.aligned.m16n8k16.row.col.f32.bf16.bf16.f32 "
        "{%0,%1,%2,%3}, {%4,%5,%6,%7}, {%8,%9}, {%0,%1,%2,%3};"
        : "+f"(c[0]), "+f"(c[1]), "+f"(c[2]), "+f"(c[3])
        : "r"(a[0]), "r"(a[1]), "r"(a[2]), "r"(a[3]), "r"(b0), "r"(b1));
}

// ---------------------------------------------------------------------------
// Setup kernels (R8 verbatim)
// ---------------------------------------------------------------------------
__global__ void deg_kernel(const int* __restrict__ dst, int* __restrict__ deg) {
    int e = blockIdx.x * blockDim.x + threadIdx.x;
    if (e < N_EDGES) atomicAdd(&deg[dst[e]], 1);
}

__global__ void scan_kernel(const int* __restrict__ deg,
                            int* __restrict__ row_start,
                            float* __restrict__ invdeg,
                            int* __restrict__ cursor) {
    __shared__ int sm[1024];
    const int t = threadIdx.x;
    const int CH = (N_NODES + 1023) / 1024;
    const int base = t * CH;
    int s = 0;
    for (int i = 0; i < CH; i++) {
        int idx = base + i;
        if (idx < N_NODES) s += deg[idx];
    }
    sm[t] = s;
    __syncthreads();
    for (int d = 1; d < 1024; d <<= 1) {
        int v = (t >= d) ? sm[t - d] : 0;
        __syncthreads();
        sm[t] += v;
        __syncthreads();
    }
    int off = sm[t] - s;
    for (int i = 0; i < CH; i++) {
        int idx = base + i;
        if (idx < N_NODES) {
            row_start[idx] = off;
            int dg = deg[idx];
            off += dg;
            invdeg[idx] = 1.0f / fmaxf((float)dg, 1.0f);
            cursor[idx] = 0;
        }
    }
    if (t == 1023) row_start[N_NODES] = off;
}

__global__ void fill_kernel(const int* __restrict__ src,
                            const int* __restrict__ dst,
                            const int* __restrict__ row_start,
                            int* __restrict__ cursor,
                            int* __restrict__ csr_src,
                            const float* __restrict__ Wl,
                            const float* __restrict__ Wr,
                            uint32_t* __restrict__ Whi,
                            uint32_t* __restrict__ Wlo) {
    int e = blockIdx.x * blockDim.x + threadIdx.x;
    if (e < N_EDGES) {
        int d = dst[e];
        int p = atomicAdd(&cursor[d], 1);
        csr_src[row_start[d] + p] = src[e];
    }
    if (e < N_LAYERS * D * ROWU32) {
        int k2 = e & (ROWU32 - 1);
        int j  = (e >> 7) & (D - 1);
        int l  = e >> 14;
        int k0 = 2 * k2, k1 = 2 * k2 + 1;
        float w0 = (k0 < D) ? Wl[(l * D + j) * D + k0] : Wr[(l * D + j) * D + (k0 - D)];
        float w1 = (k1 < D) ? Wl[(l * D + j) * D + k1] : Wr[(l * D + j) * D + (k1 - D)];
        __nv_bfloat16 h0, l0, h1, l1;
        split_bf16(w0, h0, l0);
        split_bf16(w1, h1, l1);
        Whi[e] = pack_bf16(h0, h1);
        Wlo[e] = pack_bf16(l0, l1);
    }
}

// ---------------------------------------------------------------------------
// Gather-mean -> packed bf16 hi/lo agg-half + own-x x-half (proven 62.9us)
// ---------------------------------------------------------------------------
__global__ __launch_bounds__(256)
void gather_kernel(const float4* __restrict__ x4,
                   const int* __restrict__ csr_src,
                   const int* __restrict__ row_start,
                   const float* __restrict__ invdeg,
                   uint32_t* __restrict__ Ahi,
                   uint32_t* __restrict__ Alo) {
    int warp = (blockIdx.x * blockDim.x + threadIdx.x) >> 5;
    int lane = threadIdx.x & 31;
    if (warp >= N_NODES) return;
    int b = row_start[warp];
    int e = row_start[warp + 1];
    float4 acc = make_float4(0.f, 0.f, 0.f, 0.f);
    for (int j = b; j < e; j += 32) {
        int cnt = min(32, e - j);
        int sreg = (lane < cnt) ? csr_src[j + lane] : 0;
        for (int i = 0; i < cnt; i++) {
            int si = __shfl_sync(0xffffffffu, sreg, i);
            float4 v = __ldg(x4 + (long long)si * 32 + lane);
            acc.x += v.x; acc.y += v.y; acc.z += v.z; acc.w += v.w;
        }
    }
    float sc = invdeg[warp];
    acc.x *= sc; acc.y *= sc; acc.z *= sc; acc.w *= sc;
    long long rb = (long long)warp * ROWU32;
    __nv_bfloat16 h0, l0, h1, l1, h2, l2, h3, l3;
    split_bf16(acc.x, h0, l0); split_bf16(acc.y, h1, l1);
    split_bf16(acc.z, h2, l2); split_bf16(acc.w, h3, l3);
    *(uint2*)(Ahi + rb + 2 * lane) = make_uint2(pack_bf16(h0, h1), pack_bf16(h2, h3));
    *(uint2*)(Alo + rb + 2 * lane) = make_uint2(pack_bf16(l0, l1), pack_bf16(l2, l3));
    // own x row -> x-half
    float4 mine = __ldg(x4 + (long long)warp * 32 + lane);
    split_bf16(mine.x, h0, l0); split_bf16(mine.y, h1, l1);
    split_bf16(mine.z, h2, l2); split_bf16(mine.w, h3, l3);
    *(uint2*)(Ahi + rb + 64 + 2 * lane) = make_uint2(pack_bf16(h0, h1), pack_bf16(h2, h3));
    *(uint2*)(Alo + rb + 64 + 2 * lane) = make_uint2(pack_bf16(l0, l1), pack_bf16(l2, l3));
}

// ---------------------------------------------------------------------------
// 3-term bf16 mma.sync GEMM + bias + ReLU — R8 shape (CTA 128x128, 8 warps
// 32x64, K=256 in 8 cp.async double-buffered chunks, SAP=20, 2 CTAs/SM).
// ONE CHANGE vs R8: TERM-MAJOR MMA ordering. All 16 accumulators get their
// hi*hi MMA (16 independent instrs), then all hi*lo, then all lo*hi —
// dependency spacing 1 -> 16 instrs, covering HMMA latency (R8's na-major
// order issued 3 back-to-back RAW-dependent HMMAs per accumulator).
// ---------------------------------------------------------------------------
#define SAP 20                        // uint32 row stride (16 used)
#define ARR_SZ (128 * SAP)            // 2560 uint32 = 10240 B per operand array
#define BUF_SZ (4 * ARR_SZ)           // Ah|Al|Bh|Bl
#define GEMM_SMEM (2 * BUF_SZ * 4)    // 81920 B

__global__ __launch_bounds__(256, 2)
void gemm_relu_kernel(const uint32_t* __restrict__ Ahi,
                      const uint32_t* __restrict__ Alo,
                      const uint32_t* __restrict__ Whi,
                      const uint32_t* __restrict__ Wlo,
                      const float* __restrict__ bl,
                      float* __restrict__ xout) {
    extern __shared__ uint32_t smem[];
    const uint32_t sbase = smem_u32(smem);
    const int t = threadIdx.x;
    const int lane = t & 31;
    const int w = t >> 5;
    const int wr = (w >> 1) * 32;     // warp row offset
    const int wc = (w & 1) * 64;      // warp col offset
    const int qr = lane >> 2;
    const int qc = lane & 3;
    const int row0 = blockIdx.x * 128;

    float c[2][8][4];
#pragma unroll
    for (int ma = 0; ma < 2; ma++)
#pragma unroll
        for (int na = 0; na < 8; na++)
#pragma unroll
            for (int q = 0; q < 4; q++) c[ma][na][q] = 0.0f;

    auto load_chunk = [&](int i, int b) {
        uint32_t bb = sbase + (uint32_t)(b * BUF_SZ * 4);
#pragma unroll
        for (int s = 0; s < 8; s++) {
            int slot = t + s * 256;
            int arr = slot >> 9;
            int rem = slot & 511;
            int r = rem >> 2;
            int g = rem & 3;
            uint32_t saddr = bb + (uint32_t)(arr * ARR_SZ * 4 + r * (SAP * 4) + g * 16);
            const uint32_t* gp;
            if (arr < 2) {
                int rg = row0 + r;
                if (rg >= N_NODES) rg = N_NODES - 1;
                const uint32_t* basep = arr == 0 ? Ahi : Alo;
                gp = basep + (long long)rg * ROWU32 + i * 16 + g * 4;
            } else {
                const uint32_t* basep = arr == 2 ? Whi : Wlo;
                gp = basep + r * ROWU32 + i * 16 + g * 4;
            }
            cp16(saddr, gp);
        }
        CP_COMMIT();
    };

    load_chunk(0, 0);

    for (int i = 0; i < 8; i++) {
        const int b = i & 1;
        if (i < 7) load_chunk(i + 1, b ^ 1);
        if (i < 7) CP_WAIT(1); else CP_WAIT(0);
        __syncthreads();

        const uint32_t* Ah = smem + b * BUF_SZ;
        const uint32_t* Al = Ah + ARR_SZ;
        const uint32_t* Bh = Al + ARR_SZ;
        const uint32_t* Bl = Bh + ARR_SZ;

#pragma unroll
        for (int ks = 0; ks < 2; ks++) {
            const int k2b = ks * 8;
            uint32_t ah[2][4], al[2][4];
#pragma unroll
            for (int ma = 0; ma < 2; ma++) {
                int base = (wr + ma * 16 + qr) * SAP + k2b + qc;
                ah[ma][0] = Ah[base];           al[ma][0] = Al[base];
                ah[ma][1] = Ah[base + 8 * SAP]; al[ma][1] = Al[base + 8 * SAP];
                ah[ma][2] = Ah[base + 4];       al[ma][2] = Al[base + 4];
                ah[ma][3] = Ah[base + 8 * SAP + 4]; al[ma][3] = Al[base + 8 * SAP + 4];
            }
            // ---- term 1: hi*hi for ALL 16 accumulators (independent) ----
#pragma unroll
            for (int na = 0; na < 8; na++) {
                int boff = (wc + na * 8 + qr) * SAP + k2b + qc;
                uint32_t bh0 = Bh[boff], bh1 = Bh[boff + 4];
                mma_bf16(c[0][na], ah[0], bh0, bh1);
                mma_bf16(c[1][na], ah[1], bh0, bh1);
            }
            // ---- term 2: hi*lo ----
#pragma unroll
            for (int na = 0; na < 8; na++) {
                int boff = (wc + na * 8 + qr) * SAP + k2b + qc;
                uint32_t bl0 = Bl[boff], bl1 = Bl[boff + 4];
                mma_bf16(c[0][na], ah[0], bl0, bl1);
                mma_bf16(c[1][na], ah[1], bl0, bl1);
            }
            // ---- term 3: lo*hi ----
#pragma unroll
            for (int na = 0; na < 8; na++) {
                int boff = (wc + na * 8 + qr) * SAP + k2b + qc;
                uint32_t bh0 = Bh[boff], bh1 = Bh[boff + 4];
                mma_bf16(c[0][na], al[0], bh0, bh1);
                mma_bf16(c[1][na], al[1], bh0, bh1);
            }
        }
        __syncthreads();
    }

    // ---- epilogue: bias + relu + fp32 store ----
#pragma unroll
    for (int na = 0; na < 8; na++) {
        int col = wc + na * 8 + 2 * qc;
        float b0 = __ldg(bl + col), b1 = __ldg(bl + col + 1);
#pragma unroll
        for (int ma = 0; ma < 2; ma++) {
            int r0 = row0 + wr + ma * 16 + qr;
            int r1 = r0 + 8;
            if (r0 < N_NODES) {
                float2 o;
                o.x = fmaxf(c[ma][na][0] + b0, 0.f);
                o.y = fmaxf(c[ma][na][1] + b1, 0.f);
                *(float2*)(xout + (long long)r0 * D + col) = o;
            }
            if (r1 < N_NODES) {
                float2 o;
                o.x = fmaxf(c[ma][na][2] + b0, 0.f);
                o.y = fmaxf(c[ma][na][3] + b1, 0.f);
                *(float2*)(xout + (long long)r1 * D + col) = o;
            }
        }
    }
}

// ---------------------------------------------------------------------------
// kernel_launch
// ---------------------------------------------------------------------------
extern "C" void kernel_launch(void* const* d_in, const int* in_sizes, int n_in,
                              void* d_out, int out_size) {
    const float* x  = (const float*)d_in[0];
    const int*   ei = (const int*)  d_in[1];
    const float* Wl = (const float*)d_in[2];
    const float* bl = (const float*)d_in[3];
    const float* Wr = (const float*)d_in[4];
    float* out = (float*)d_out;

    const int* src = ei;
    const int* dst = ei + N_EDGES;

    float *bufA, *bufB, *invdeg;
    int *deg, *cursor, *rowstart, *csr_src;
    uint32_t *ahi, *alo, *whi, *wlo;
    cudaGetSymbolAddress((void**)&bufA,     g_bufA);
    cudaGetSymbolAddress((void**)&bufB,     g_bufB);
    cudaGetSymbolAddress((void**)&invdeg,   g_invdeg);
    cudaGetSymbolAddress((void**)&deg,      g_deg);
    cudaGetSymbolAddress((void**)&cursor,   g_cursor);
    cudaGetSymbolAddress((void**)&rowstart, g_rowstart);
    cudaGetSymbolAddress((void**)&csr_src,  g_csr_src);
    cudaGetSymbolAddress((void**)&ahi,      g_Ahi);
    cudaGetSymbolAddress((void**)&alo,      g_Alo);
    cudaGetSymbolAddress((void**)&whi,      g_Whi);
    cudaGetSymbolAddress((void**)&wlo,      g_Wlo);

    cudaFuncSetAttribute(gemm_relu_kernel,
                         cudaFuncAttributeMaxDynamicSharedMemorySize, GEMM_SMEM);

    cudaMemsetAsync(deg, 0, N_NODES * sizeof(int));
    deg_kernel<<<(N_EDGES + 255) / 256, 256>>>(dst, deg);
    scan_kernel<<<1, 1024>>>(deg, rowstart, invdeg, cursor);
    fill_kernel<<<(N_EDGES + 255) / 256, 256>>>(src, dst, rowstart,
                                                cursor, csr_src,
                                                Wl, Wr, whi, wlo);

    const int gather_blocks = (N_NODES * 32 + 255) / 256;
    const int gemm_blocks = (N_NODES + 127) / 128;

    const float* cur = x;
    float* outs[N_LAYERS] = {bufA, bufB, bufA, out};

    for (int l = 0; l < N_LAYERS; l++) {
        gather_kernel<<<gather_blocks, 256>>>((const float4*)cur, csr_src,
                                              rowstart, invdeg, ahi, alo);
        gemm_relu_kernel<<<gemm_blocks, 256, GEMM_SMEM>>>(
            ahi, alo,
            whi + (size_t)l * D * ROWU32,
            wlo + (size_t)l * D * ROWU32,
            bl + (size_t)l * D,
            outs[l]);
        cur = outs[l];
    }
}

// round 15
// speedup vs baseline: 1.7780x; 1.1269x over previous
#include <cuda_runtime.h>
#include <cuda_fp16.h>
#include <cstdint>

#define N_NODES 100000
#define N_EDGES 1600000
#define D 128
#define N_LAYERS 4
#define ROWU32 128          // 256 fp16 per activation row = 128 uint32

// ---------------- scratch (__device__ globals; no allocation) ----------------
__device__ float g_bufA[N_NODES * D];
__device__ float g_bufB[N_NODES * D];
__device__ float g_invdeg[N_NODES];
__device__ int   g_deg[N_NODES];
__device__ int   g_cursor[N_NODES];
__device__ int   g_rowstart[N_NODES + 1];
__device__ int   g_csr_src[N_EDGES];
// Packed fp16 activations [row][k2]: k2<64 = agg-half, >=64 = x-half
__device__ uint32_t g_Ahi[(size_t)N_NODES * ROWU32];
__device__ uint32_t g_Alo[(size_t)N_NODES * ROWU32];
// Packed fp16 weights [l][j][k2] combined (k<128 -> Wl, k>=128 -> Wr), single-rounded
__device__ uint32_t g_Wh[N_LAYERS * D * ROWU32];

// ------------------------------ helpers -------------------------------------
__device__ __forceinline__ uint32_t smem_u32(const void* p) {
    uint32_t a;
    asm("{ .reg .u64 t; cvta.to.shared.u64 t, %1; cvt.u32.u64 %0, t; }"
        : "=r"(a) : "l"(p));
    return a;
}
__device__ __forceinline__ void cp16(uint32_t saddr, const void* g) {
    asm volatile("cp.async.ca.shared.global [%0], [%1], 16;"
                 :: "r"(saddr), "l"(g) : "memory");
}
#define CP_COMMIT() asm volatile("cp.async.commit_group;" ::: "memory")
#define CP_WAIT(n)  asm volatile("cp.async.wait_group %0;" :: "n"(n) : "memory")

__device__ __forceinline__ uint32_t pack_h2(__half a, __half b) {
    return ((uint32_t)__half_as_ushort(b) << 16) | (uint32_t)__half_as_ushort(a);
}
__device__ __forceinline__ void split_fp16(float x, __half& h, __half& l) {
    h = __float2half(x);
    l = __float2half(x - __half2float(h));
}

__device__ __forceinline__ void mma_fp16(float c[4], const uint32_t a[4],
                                         uint32_t b0, uint32_t b1) {
    asm volatile(
        "mma.sync.aligned.m16n8k16.row.col.f32.f16.f16.f32 "
        "{%0,%1,%2,%3}, {%4,%5,%6,%7}, {%8,%9}, {%0,%1,%2,%3};"
        : "+f"(c[0]), "+f"(c[1]), "+f"(c[2]), "+f"(c[3])
        : "r"(a[0]), "r"(a[1]), "r"(a[2]), "r"(a[3]), "r"(b0), "r"(b1));
}

// ---------------------------------------------------------------------------
// Setup kernels
// ---------------------------------------------------------------------------
__global__ void deg_kernel(const int* __restrict__ dst, int* __restrict__ deg) {
    int e = blockIdx.x * blockDim.x + threadIdx.x;
    if (e < N_EDGES) atomicAdd(&deg[dst[e]], 1);
}

__global__ void scan_kernel(const int* __restrict__ deg,
                            int* __restrict__ row_start,
                            float* __restrict__ invdeg,
                            int* __restrict__ cursor) {
    __shared__ int sm[1024];
    const int t = threadIdx.x;
    const int CH = (N_NODES + 1023) / 1024;
    const int base = t * CH;
    int s = 0;
    for (int i = 0; i < CH; i++) {
        int idx = base + i;
        if (idx < N_NODES) s += deg[idx];
    }
    sm[t] = s;
    __syncthreads();
    for (int d = 1; d < 1024; d <<= 1) {
        int v = (t >= d) ? sm[t - d] : 0;
        __syncthreads();
        sm[t] += v;
        __syncthreads();
    }
    int off = sm[t] - s;
    for (int i = 0; i < CH; i++) {
        int idx = base + i;
        if (idx < N_NODES) {
            row_start[idx] = off;
            int dg = deg[idx];
            off += dg;
            invdeg[idx] = 1.0f / fmaxf((float)dg, 1.0f);
            cursor[idx] = 0;
        }
    }
    if (t == 1023) row_start[N_NODES] = off;
}

// fill: CSR fill + W single-fp16 pack
__global__ void fill_kernel(const int* __restrict__ src,
                            const int* __restrict__ dst,
                            const int* __restrict__ row_start,
                            int* __restrict__ cursor,
                            int* __restrict__ csr_src,
                            const float* __restrict__ Wl,
                            const float* __restrict__ Wr,
                            uint32_t* __restrict__ Wh) {
    int e = blockIdx.x * blockDim.x + threadIdx.x;
    if (e < N_EDGES) {
        int d = dst[e];
        int p = atomicAdd(&cursor[d], 1);
        csr_src[row_start[d] + p] = src[e];
    }
    if (e < N_LAYERS * D * ROWU32) {
        int k2 = e & (ROWU32 - 1);
        int j  = (e >> 7) & (D - 1);
        int l  = e >> 14;
        int k0 = 2 * k2, k1 = 2 * k2 + 1;
        float w0 = (k0 < D) ? Wl[(l * D + j) * D + k0] : Wr[(l * D + j) * D + (k0 - D)];
        float w1 = (k1 < D) ? Wl[(l * D + j) * D + k1] : Wr[(l * D + j) * D + (k1 - D)];
        Wh[e] = pack_h2(__float2half(w0), __float2half(w1));
    }
}

// ---------------------------------------------------------------------------
// Gather-mean -> packed fp16 hi/lo agg-half + own-x x-half
// ---------------------------------------------------------------------------
__global__ __launch_bounds__(256)
void gather_kernel(const float4* __restrict__ x4,
                   const int* __restrict__ csr_src,
                   const int* __restrict__ row_start,
                   const float* __restrict__ invdeg,
                   uint32_t* __restrict__ Ahi,
                   uint32_t* __restrict__ Alo) {
    int warp = (blockIdx.x * blockDim.x + threadIdx.x) >> 5;
    int lane = threadIdx.x & 31;
    if (warp >= N_NODES) return;
    int b = row_start[warp];
    int e = row_start[warp + 1];
    float4 acc = make_float4(0.f, 0.f, 0.f, 0.f);
    for (int j = b; j < e; j += 32) {
        int cnt = min(32, e - j);
        int sreg = (lane < cnt) ? csr_src[j + lane] : 0;
        for (int i = 0; i < cnt; i++) {
            int si = __shfl_sync(0xffffffffu, sreg, i);
            float4 v = __ldg(x4 + (long long)si * 32 + lane);
            acc.x += v.x; acc.y += v.y; acc.z += v.z; acc.w += v.w;
        }
    }
    float sc = invdeg[warp];
    acc.x *= sc; acc.y *= sc; acc.z *= sc; acc.w *= sc;
    long long rb = (long long)warp * ROWU32;
    __half h0, l0, h1, l1, h2, l2, h3, l3;
    split_fp16(acc.x, h0, l0); split_fp16(acc.y, h1, l1);
    split_fp16(acc.z, h2, l2); split_fp16(acc.w, h3, l3);
    *(uint2*)(Ahi + rb + 2 * lane) = make_uint2(pack_h2(h0, h1), pack_h2(h2, h3));
    *(uint2*)(Alo + rb + 2 * lane) = make_uint2(pack_h2(l0, l1), pack_h2(l2, l3));
    // own x row -> x-half
    float4 mine = __ldg(x4 + (long long)warp * 32 + lane);
    split_fp16(mine.x, h0, l0); split_fp16(mine.y, h1, l1);
    split_fp16(mine.z, h2, l2); split_fp16(mine.w, h3, l3);
    *(uint2*)(Ahi + rb + 64 + 2 * lane) = make_uint2(pack_h2(h0, h1), pack_h2(h2, h3));
    *(uint2*)(Alo + rb + 64 + 2 * lane) = make_uint2(pack_h2(l0, l1), pack_h2(l2, l3));
}

// ---------------------------------------------------------------------------
// 2-term fp16 mma.sync GEMM + bias + ReLU — R14 structure (CTA 128x128,
// 8 warps 32x64, K=256 in 8 cp.async double-buffered chunks, SAP=20,
// term-major ordering). ONE CHANGE: 2 terms (Ah*Bh + Al*Bh), W single fp16.
// HMMA count 96 -> 64 per warp-chunk; smem 3 arrays instead of 4.
// ---------------------------------------------------------------------------
#define SAP 20                        // uint32 row stride (16 used)
#define ARR_SZ (128 * SAP)            // 2560 uint32 = 10240 B per operand array
#define BUF_SZ (3 * ARR_SZ)           // Ah|Al|Bh
#define GEMM_SMEM (2 * BUF_SZ * 4)    // 61440 B

__global__ __launch_bounds__(256, 2)
void gemm_relu_kernel(const uint32_t* __restrict__ Ahi,
                      const uint32_t* __restrict__ Alo,
                      const uint32_t* __restrict__ Wh,
                      const float* __restrict__ bl,
                      float* __restrict__ xout) {
    extern __shared__ uint32_t smem[];
    const uint32_t sbase = smem_u32(smem);
    const int t = threadIdx.x;
    const int lane = t & 31;
    const int w = t >> 5;
    const int wr = (w >> 1) * 32;     // warp row offset
    const int wc = (w & 1) * 64;      // warp col offset
    const int qr = lane >> 2;
    const int qc = lane & 3;
    const int row0 = blockIdx.x * 128;

    float c[2][8][4];
#pragma unroll
    for (int ma = 0; ma < 2; ma++)
#pragma unroll
        for (int na = 0; na < 8; na++)
#pragma unroll
            for (int q = 0; q < 4; q++) c[ma][na][q] = 0.0f;

    auto load_chunk = [&](int i, int b) {
        uint32_t bb = sbase + (uint32_t)(b * BUF_SZ * 4);
#pragma unroll
        for (int s = 0; s < 6; s++) {
            int slot = t + s * 256;       // 0..1535 (3 arrays x 512)
            int arr = slot >> 9;          // 0=Ahi 1=Alo 2=Wh
            int rem = slot & 511;
            int r = rem >> 2;             // 0..127
            int g = rem & 3;
            uint32_t saddr = bb + (uint32_t)(arr * ARR_SZ * 4 + r * (SAP * 4) + g * 16);
            const uint32_t* gp;
            if (arr < 2) {
                int rg = row0 + r;
                if (rg >= N_NODES) rg = N_NODES - 1;
                const uint32_t* basep = arr == 0 ? Ahi : Alo;
                gp = basep + (long long)rg * ROWU32 + i * 16 + g * 4;
            } else {
                gp = Wh + r * ROWU32 + i * 16 + g * 4;
            }
            cp16(saddr, gp);
        }
        CP_COMMIT();
    };

    load_chunk(0, 0);

    for (int i = 0; i < 8; i++) {
        const int b = i & 1;
        if (i < 7) load_chunk(i + 1, b ^ 1);
        if (i < 7) CP_WAIT(1); else CP_WAIT(0);
        __syncthreads();

        const uint32_t* Ah = smem + b * BUF_SZ;
        const uint32_t* Al = Ah + ARR_SZ;
        const uint32_t* Bh = Al + ARR_SZ;

#pragma unroll
        for (int ks = 0; ks < 2; ks++) {
            const int k2b = ks * 8;
            uint32_t ah[2][4], al[2][4];
#pragma unroll
            for (int ma = 0; ma < 2; ma++) {
                int base = (wr + ma * 16 + qr) * SAP + k2b + qc;
                ah[ma][0] = Ah[base];           al[ma][0] = Al[base];
                ah[ma][1] = Ah[base + 8 * SAP]; al[ma][1] = Al[base + 8 * SAP];
                ah[ma][2] = Ah[base + 4];       al[ma][2] = Al[base + 4];
                ah[ma][3] = Ah[base + 8 * SAP + 4]; al[ma][3] = Al[base + 8 * SAP + 4];
            }
            // ---- term 1: Ah*Bh for all 16 accumulators (independent) ----
#pragma unroll
            for (int na = 0; na < 8; na++) {
                int boff = (wc + na * 8 + qr) * SAP + k2b + qc;
                uint32_t bh0 = Bh[boff], bh1 = Bh[boff + 4];
                mma_fp16(c[0][na], ah[0], bh0, bh1);
                mma_fp16(c[1][na], ah[1], bh0, bh1);
            }
            // ---- term 2: Al*Bh ----
#pragma unroll
            for (int na = 0; na < 8; na++) {
                int boff = (wc + na * 8 + qr) * SAP + k2b + qc;
                uint32_t bh0 = Bh[boff], bh1 = Bh[boff + 4];
                mma_fp16(c[0][na], al[0], bh0, bh1);
                mma_fp16(c[1][na], al[1], bh0, bh1);
            }
        }
        __syncthreads();
    }

    // ---- epilogue: bias + relu + fp32 store ----
#pragma unroll
    for (int na = 0; na < 8; na++) {
        int col = wc + na * 8 + 2 * qc;
        float b0 = __ldg(bl + col), b1 = __ldg(bl + col + 1);
#pragma unroll
        for (int ma = 0; ma < 2; ma++) {
            int r0 = row0 + wr + ma * 16 + qr;
            int r1 = r0 + 8;
            if (r0 < N_NODES) {
                float2 o;
                o.x = fmaxf(c[ma][na][0] + b0, 0.f);
                o.y = fmaxf(c[ma][na][1] + b1, 0.f);
                *(float2*)(xout + (long long)r0 * D + col) = o;
            }
            if (r1 < N_NODES) {
                float2 o;
                o.x = fmaxf(c[ma][na][2] + b0, 0.f);
                o.y = fmaxf(c[ma][na][3] + b1, 0.f);
                *(float2*)(xout + (long long)r1 * D + col) = o;
            }
        }
    }
}

// ---------------------------------------------------------------------------
// kernel_launch
// ---------------------------------------------------------------------------
extern "C" void kernel_launch(void* const* d_in, const int* in_sizes, int n_in,
                              void* d_out, int out_size) {
    const float* x  = (const float*)d_in[0];
    const int*   ei = (const int*)  d_in[1];
    const float* Wl = (const float*)d_in[2];
    const float* bl = (const float*)d_in[3];
    const float* Wr = (const float*)d_in[4];
    float* out = (float*)d_out;

    const int* src = ei;
    const int* dst = ei + N_EDGES;

    float *bufA, *bufB, *invdeg;
    int *deg, *cursor, *rowstart, *csr_src;
    uint32_t *ahi, *alo, *wh;
    cudaGetSymbolAddress((void**)&bufA,     g_bufA);
    cudaGetSymbolAddress((void**)&bufB,     g_bufB);
    cudaGetSymbolAddress((void**)&invdeg,   g_invdeg);
    cudaGetSymbolAddress((void**)&deg,      g_deg);
    cudaGetSymbolAddress((void**)&cursor,   g_cursor);
    cudaGetSymbolAddress((void**)&rowstart, g_rowstart);
    cudaGetSymbolAddress((void**)&csr_src,  g_csr_src);
    cudaGetSymbolAddress((void**)&ahi,      g_Ahi);
    cudaGetSymbolAddress((void**)&alo,      g_Alo);
    cudaGetSymbolAddress((void**)&wh,       g_Wh);

    cudaFuncSetAttribute(gemm_relu_kernel,
                         cudaFuncAttributeMaxDynamicSharedMemorySize, GEMM_SMEM);

    cudaMemsetAsync(deg, 0, N_NODES * sizeof(int));
    deg_kernel<<<(N_EDGES + 255) / 256, 256>>>(dst, deg);
    scan_kernel<<<1, 1024>>>(deg, rowstart, invdeg, cursor);
    fill_kernel<<<(N_EDGES + 255) / 256, 256>>>(src, dst, rowstart,
                                                cursor, csr_src,
                                                Wl, Wr, wh);

    const int gather_blocks = (N_NODES * 32 + 255) / 256;
    const int gemm_blocks = (N_NODES + 127) / 128;

    const float* cur = x;
    float* outs[N_LAYERS] = {bufA, bufB, bufA, out};

    for (int l = 0; l < N_LAYERS; l++) {
        gather_kernel<<<gather_blocks, 256>>>((const float4*)cur, csr_src,
                                              rowstart, invdeg, ahi, alo);
        gemm_relu_kernel<<<gemm_blocks, 256, GEMM_SMEM>>>(
            ahi, alo,
            wh + (size_t)l * D * ROWU32,
            bl + (size_t)l * D,
            outs[l]);
        cur = outs[l];
    }
}